// round 1
// baseline (speedup 1.0000x reference)
#include <cuda_runtime.h>
#include <math.h>
#include <stdint.h>

// ---------------- problem constants ----------------
#define BB   8
#define SEQ  10          // "C" in reference (sequence length)
#define FD   48          // DIM == C_IN
#define HH   64
#define WW   64
#define HWN  4096        // H*W
#define NSEQ 32768       // B*H*W  (number of sequences)
#define TOK  327680      // NSEQ*SEQ == pixels (80*4096)
#define HEADS 8
#define HD    6
#define MLPD  192
#define CH    96         // 2*C_IN
#define PWH   384        // 8*C_IN

// ---------------- scratch (device globals; no allocation) ----------------
__device__ float g_t  [(size_t)TOK * 48];    //  63 MB  token states
__device__ float g_qkv[(size_t)TOK * 144];   // 189 MB
__device__ float g_o  [(size_t)TOK * 48];    //  63 MB
__device__ float g_h  [(size_t)TOK * 384];   // 503 MB  (h1 / U reuse)
__device__ float g_cat[(size_t)TOK * 96];    // 126 MB  channels-last cat
__device__ float g_z  [(size_t)TOK * 96];    // 126 MB  dwconv (+LN in-place)
__device__ float g_res[(size_t)TOK * 48];    //  63 MB  sc + v (channels-last)
__device__ float g_scw[96 * 48];             // sc_w transposed

// ---------------- helpers ----------------
__device__ __forceinline__ float gelu_exact(float v) {
    return 0.5f * v * (1.0f + erff(v * 0.70710678118654752f));
}

// ---------------- generic tiled SGEMM: C[M x N] (+)= A[M x K] @ W[K x N] + bias ----------------
// BM=64, BN=64, BK=16; 256 threads; 4x4 micro-tile. M must be a multiple of 64.
template<int K, int N, bool GELU, bool ACC>
__global__ void __launch_bounds__(256) gemm_k(const float* __restrict__ A,
                                              const float* __restrict__ W,
                                              const float* __restrict__ bias,
                                              float* __restrict__ C) {
    __shared__ float As[16][64];   // [k][row]
    __shared__ float Bs[16][64];   // [k][col]
    const int tid  = threadIdx.x;
    const int row0 = blockIdx.x * 64;
    const int col0 = blockIdx.y * 64;
    const int tx = tid & 15, ty = tid >> 4;

    const int a_row = tid >> 2;          // 0..63
    const int a_k4  = (tid & 3) << 2;    // 0,4,8,12
    const int b_k   = tid >> 4;          // 0..15
    const int b_c4  = (tid & 15) << 2;   // 0..60

    float acc[4][4];
#pragma unroll
    for (int i = 0; i < 4; i++)
#pragma unroll
        for (int j = 0; j < 4; j++) acc[i][j] = 0.f;

    for (int k0 = 0; k0 < K; k0 += 16) {
        float4 av = *(const float4*)(A + (size_t)(row0 + a_row) * K + k0 + a_k4);
        float4 bv = make_float4(0.f, 0.f, 0.f, 0.f);
        if (col0 + b_c4 < N)
            bv = *(const float4*)(W + (size_t)(k0 + b_k) * N + col0 + b_c4);
        __syncthreads();
        As[a_k4 + 0][a_row] = av.x;
        As[a_k4 + 1][a_row] = av.y;
        As[a_k4 + 2][a_row] = av.z;
        As[a_k4 + 3][a_row] = av.w;
        *(float4*)&Bs[b_k][b_c4] = bv;
        __syncthreads();
#pragma unroll
        for (int kk = 0; kk < 16; kk++) {
            float4 a = *(float4*)&As[kk][ty * 4];
            float4 b = *(float4*)&Bs[kk][tx * 4];
            float ar[4] = {a.x, a.y, a.z, a.w};
            float br[4] = {b.x, b.y, b.z, b.w};
#pragma unroll
            for (int i = 0; i < 4; i++)
#pragma unroll
                for (int j = 0; j < 4; j++) acc[i][j] = fmaf(ar[i], br[j], acc[i][j]);
        }
    }

#pragma unroll
    for (int i = 0; i < 4; i++) {
        const int r = row0 + ty * 4 + i;
#pragma unroll
        for (int j = 0; j < 4; j++) {
            const int c = col0 + tx * 4 + j;
            if (c < N) {
                float v = acc[i][j] + bias[c];
                if (GELU) v = gelu_exact(v);
                float* p = C + (size_t)r * N + c;
                if (ACC) v += *p;
                *p = v;
            }
        }
    }
}

// ---------------- transposes ----------------
// x(B,10,48,H,W) -> t[(b*HW+hw)][s*48+f]   (per-b 480x4096 transpose)
__global__ void k_tin(const float* __restrict__ x) {
    __shared__ float sm[32][33];
    const int cf0 = blockIdx.x * 32, hw0 = blockIdx.y * 32, b = blockIdx.z;
    const int tx = threadIdx.x, ty = threadIdx.y;
#pragma unroll
    for (int yy = 0; yy < 4; yy++) {
        int cf = cf0 + ty + yy * 8;
        sm[ty + yy * 8][tx] = x[((size_t)b * 480 + cf) * 4096 + hw0 + tx];
    }
    __syncthreads();
#pragma unroll
    for (int yy = 0; yy < 4; yy++) {
        int hw = hw0 + ty + yy * 8;
        g_t[((size_t)b * 4096 + hw) * 480 + cf0 + tx] = sm[tx][ty + yy * 8];
    }
}

// cat channels-last: first 48 channels from x (per-n 48x4096 transpose)
__global__ void k_catx(const float* __restrict__ x) {
    __shared__ float sm[32][33];
    const int c0 = blockIdx.x * 32, hw0 = blockIdx.y * 32, n = blockIdx.z;
    const int tx = threadIdx.x, ty = threadIdx.y;
#pragma unroll
    for (int yy = 0; yy < 4; yy++) {
        int c = c0 + ty + yy * 8;
        if (c < 48)
            sm[ty + yy * 8][tx] = x[((size_t)n * 48 + c) * 4096 + hw0 + tx];
    }
    __syncthreads();
#pragma unroll
    for (int yy = 0; yy < 4; yy++) {
        int hw = hw0 + ty + yy * 8;
        int c = c0 + tx;
        if (c < 48)
            g_cat[((size_t)n * 4096 + hw) * 96 + c] = sm[tx][ty + yy * 8];
    }
}

// cat channels-last: last 48 channels from final t
__global__ void k_catt() {
    size_t idx = (size_t)blockIdx.x * 256 + threadIdx.x;
    if (idx >= (size_t)TOK * 48) return;
    int f = (int)(idx % 48);
    size_t p = idx / 48;              // pixel index: n*4096 + hw
    int hw = (int)(p & 4095);
    int n = (int)(p >> 12);
    int b = n / 10, s = n % 10;
    g_cat[p * 96 + 48 + f] = g_t[(((size_t)b * 4096 + hw) * 10 + s) * 48 + f];
}

// sc_w (48,96) -> g_scw (96,48)
__global__ void k_scw(const float* __restrict__ scw) {
    int idx = blockIdx.x * 256 + threadIdx.x;
    if (idx < 96 * 48) {
        int c = idx / 48, o = idx % 48;
        g_scw[c * 48 + o] = scw[o * 96 + c];
    }
}

// res (n, hw, 48) -> out (n, 48, hw)
__global__ void k_tout(float* __restrict__ out) {
    __shared__ float sm[32][33];
    const int hw0 = blockIdx.x * 32, c0 = blockIdx.y * 32, n = blockIdx.z;
    const int tx = threadIdx.x, ty = threadIdx.y;
#pragma unroll
    for (int yy = 0; yy < 4; yy++) {
        int c = c0 + tx;
        if (c < 48)
            sm[ty + yy * 8][tx] = g_res[((size_t)n * 4096 + hw0 + ty + yy * 8) * 48 + c];
    }
    __syncthreads();
#pragma unroll
    for (int yy = 0; yy < 4; yy++) {
        int c = c0 + ty + yy * 8;
        if (c < 48)
            out[((size_t)n * 48 + c) * 4096 + hw0 + tx] = sm[tx][ty + yy * 8];
    }
}

// ---------------- banded attention (|i-j|<=1), 16 sequences per block ----------------
__global__ void __launch_bounds__(256) k_attn() {
    extern __shared__ float sm[];
    float* sq = sm;            // 16*10*144
    float* so = sm + 23040;    // 16*10*48
    const int tid = threadIdx.x;
    const size_t tok0 = (size_t)blockIdx.x * 160;

    for (int i = tid; i < 23040; i += 256) sq[i] = g_qkv[tok0 * 144 + i];
    __syncthreads();

    if (tid < 128) {
        const int sl = tid >> 3, hh = tid & 7;
        const float* base = sq + sl * 1440;
        const float scale = 0.40824829046386301637f;  // 6^-0.5
        for (int i = 0; i < SEQ; i++) {
            const float* ki = base + i * 144 + 48 + hh * 6;
            int jlo = (i > 0) ? i - 1 : 0;
            int jhi = (i < SEQ - 1) ? i + 1 : SEQ - 1;
            float lg[3];
            float mx = -1e30f;
            for (int j = jlo; j <= jhi; j++) {
                const float* qj = base + j * 144 + hh * 6;
                float d = 0.f;
#pragma unroll
                for (int dd = 0; dd < 6; dd++) d += ki[dd] * qj[dd];
                d *= scale;
                lg[j - jlo] = d;
                mx = fmaxf(mx, d);
            }
            float se = 0.f;
            for (int j = jlo; j <= jhi; j++) {
                lg[j - jlo] = expf(lg[j - jlo] - mx);
                se += lg[j - jlo];
            }
            float inv = 1.f / se;
#pragma unroll
            for (int dd = 0; dd < 6; dd++) {
                float o = 0.f;
                for (int j = jlo; j <= jhi; j++)
                    o += lg[j - jlo] * base[j * 144 + 96 + hh * 6 + dd];
                so[(sl * 10 + i) * 48 + hh * 6 + dd] = o * inv;
            }
        }
    }
    __syncthreads();
    for (int i = tid; i < 7680; i += 256) g_o[tok0 * 48 + i] = so[i];
}

// ---------------- depthwise 3x3 conv (channels-last), weights in smem ----------------
__global__ void __launch_bounds__(256) k_dw(const float* __restrict__ wdw,
                                            const float* __restrict__ bdw) {
    __shared__ float sw[864];
    __shared__ float sb[96];
    for (int i = threadIdx.x; i < 864; i += 256) sw[i] = wdw[i];
    for (int i = threadIdx.x; i < 96; i += 256) sb[i] = bdw[i];
    __syncthreads();

    size_t idx = (size_t)blockIdx.x * 256 + threadIdx.x;   // 80*4096*24
    int c4 = (int)(idx % 24);
    size_t p = idx / 24;
    int w = (int)(p & 63);
    int h = (int)((p >> 6) & 63);
    int n = (int)(p >> 12);
    int c = c4 * 4;

    float4 acc = make_float4(sb[c], sb[c + 1], sb[c + 2], sb[c + 3]);
#pragma unroll
    for (int ky = 0; ky < 3; ky++) {
        int hh = h + ky - 1;
        if (hh < 0 || hh >= 64) continue;
#pragma unroll
        for (int kx = 0; kx < 3; kx++) {
            int ww = w + kx - 1;
            if (ww < 0 || ww >= 64) continue;
            const float4 v = *(const float4*)(g_cat + (((size_t)n * 4096 + hh * 64 + ww) * 96 + c));
            int wi = ky * 3 + kx;
            acc.x = fmaf(v.x, sw[(c + 0) * 9 + wi], acc.x);
            acc.y = fmaf(v.y, sw[(c + 1) * 9 + wi], acc.y);
            acc.z = fmaf(v.z, sw[(c + 2) * 9 + wi], acc.z);
            acc.w = fmaf(v.w, sw[(c + 3) * 9 + wi], acc.w);
        }
    }
    *(float4*)(g_z + p * 96 + c) = acc;
}

// ---------------- LayerNorm over 96 channels (warp per row, in-place on g_z) ----------------
__global__ void __launch_bounds__(128) k_ln(const float* __restrict__ gam,
                                            const float* __restrict__ bet) {
    const int row = blockIdx.x * 4 + (threadIdx.x >> 5);
    const int lane = threadIdx.x & 31;
    float* z = g_z + (size_t)row * 96;
    float x0 = z[lane], x1 = z[lane + 32], x2 = z[lane + 64];
    float s = x0 + x1 + x2;
#pragma unroll
    for (int o = 16; o; o >>= 1) s += __shfl_xor_sync(0xffffffffu, s, o);
    float mu = s * (1.f / 96.f);
    float d0 = x0 - mu, d1 = x1 - mu, d2 = x2 - mu;
    float q = d0 * d0 + d1 * d1 + d2 * d2;
#pragma unroll
    for (int o = 16; o; o >>= 1) q += __shfl_xor_sync(0xffffffffu, q, o);
    float rs = rsqrtf(q * (1.f / 96.f) + 1e-6f);
    z[lane]      = d0 * rs * gam[lane]      + bet[lane];
    z[lane + 32] = d1 * rs * gam[lane + 32] + bet[lane + 32];
    z[lane + 64] = d2 * rs * gam[lane + 64] + bet[lane + 64];
}

// ---------------- host launcher ----------------
extern "C" void kernel_launch(void* const* d_in, const int* in_sizes, int n_in,
                              void* d_out, int out_size) {
    const float* x      = (const float*)d_in[0];
    const float* qkv_w  = (const float*)d_in[1];
    const float* qkv_b  = (const float*)d_in[2];
    const float* proj_w = (const float*)d_in[3];
    const float* proj_b = (const float*)d_in[4];
    const float* ff1_w  = (const float*)d_in[5];
    const float* ff1_b  = (const float*)d_in[6];
    const float* ff2_w  = (const float*)d_in[7];
    const float* ff2_b  = (const float*)d_in[8];
    const float* dw_w   = (const float*)d_in[9];
    const float* dw_b   = (const float*)d_in[10];
    const float* ln_g   = (const float*)d_in[11];
    const float* ln_b   = (const float*)d_in[12];
    const float* pw1_w  = (const float*)d_in[13];
    const float* pw1_b  = (const float*)d_in[14];
    const float* pw2_w  = (const float*)d_in[15];
    const float* pw2_b  = (const float*)d_in[16];
    const float* sc_w   = (const float*)d_in[17];
    const float* sc_b   = (const float*)d_in[18];
    float* out = (float*)d_out;

    static float *pt = nullptr, *pqkv, *po, *ph, *pcat, *pz, *pres, *pscw;
    static bool init = false;
    if (!init) {
        cudaGetSymbolAddress((void**)&pt,   g_t);
        cudaGetSymbolAddress((void**)&pqkv, g_qkv);
        cudaGetSymbolAddress((void**)&po,   g_o);
        cudaGetSymbolAddress((void**)&ph,   g_h);
        cudaGetSymbolAddress((void**)&pcat, g_cat);
        cudaGetSymbolAddress((void**)&pz,   g_z);
        cudaGetSymbolAddress((void**)&pres, g_res);
        cudaGetSymbolAddress((void**)&pscw, g_scw);
        cudaFuncSetAttribute(k_attn, cudaFuncAttributeMaxDynamicSharedMemorySize, 122880);
        init = true;
    }

    const dim3 tb32(32, 8);
    // x -> t
    k_tin<<<dim3(15, 128, BB), tb32>>>(x);

    // 2 transformer layers
    for (int l = 0; l < 2; l++) {
        gemm_k<48, 144, false, false><<<dim3(5120, 3), 256>>>(pt, qkv_w + l * 48 * 144, qkv_b + l * 144, pqkv);
        k_attn<<<2048, 256, 122880>>>();
        gemm_k<48, 48, false, true><<<dim3(5120, 1), 256>>>(po, proj_w + l * 48 * 48, proj_b + l * 48, pt);
        gemm_k<48, 192, true, false><<<dim3(5120, 3), 256>>>(pt, ff1_w + l * 48 * 192, ff1_b + l * 192, ph);
        gemm_k<192, 48, false, true><<<dim3(5120, 1), 256>>>(ph, ff2_w + l * 192 * 48, ff2_b + l * 48, pt);
    }

    // build channels-last cat = [x ; y]
    k_catx<<<dim3(2, 128, 80), tb32>>>(x);
    k_catt<<<61440, 256>>>();
    k_scw<<<18, 256>>>(sc_w);

    // dwconv + LN
    k_dw<<<30720, 256>>>(dw_w, dw_b);
    k_ln<<<81920, 128>>>(ln_g, ln_b);

    // sc shortcut, then pointwise MLP accumulated on top
    gemm_k<96, 48, false, false><<<dim3(5120, 1), 256>>>(pcat, pscw, sc_b, pres);
    gemm_k<96, 384, true, false><<<dim3(5120, 6), 256>>>(pz, pw1_w, pw1_b, ph);
    gemm_k<384, 48, false, true><<<dim3(5120, 1), 256>>>(ph, pw2_w, pw2_b, pres);

    // final layout: (n, hw, 48) -> (n, 48, hw) == (B,10,48,H,W)
    k_tout<<<dim3(128, 2, 80), tb32>>>(out);
}

// round 2
// speedup vs baseline: 1.4413x; 1.4413x over previous
#include <cuda_runtime.h>
#include <math.h>
#include <stdint.h>

// ---------------- problem constants ----------------
#define BB   8
#define SEQ  10
#define TOK  327680      // B*H*W*SEQ tokens == pixels*F

// ---------------- scratch (device globals; no allocation) ----------------
__device__ float g_t  [(size_t)TOK * 48];
__device__ float g_qkv[(size_t)TOK * 144];
__device__ float g_o  [(size_t)TOK * 48];
__device__ float g_h  [(size_t)TOK * 384];
__device__ float g_cat[(size_t)TOK * 96];
__device__ float g_z  [(size_t)TOK * 96];
__device__ float g_res[(size_t)TOK * 48];
__device__ float g_scw[96 * 48];

__device__ __forceinline__ float gelu_exact(float v) {
    return 0.5f * v * (1.0f + erff(v * 0.70710678118654752f));
}
__device__ __forceinline__ uint32_t f2tf(float f) {
    uint32_t u;
    asm("cvt.rna.tf32.f32 %0, %1;" : "=r"(u) : "f"(f));
    return u;
}

#define MMA_TF32(c, a0, a1, a2, a3, b0, b1)                                 \
    asm volatile("mma.sync.aligned.m16n8k8.row.col.f32.tf32.tf32.f32 "     \
                 "{%0,%1,%2,%3}, {%4,%5,%6,%7}, {%8,%9}, {%0,%1,%2,%3};\n" \
                 : "+f"(c[0]), "+f"(c[1]), "+f"(c[2]), "+f"(c[3])          \
                 : "r"(a0), "r"(a1), "r"(a2), "r"(a3), "r"(b0), "r"(b1))

// ---------------- TF32 tensor-core GEMM: C[Mx N] (+)= A[MxK] @ W[KxN] + bias ----------
// BM=128, BN=48, BK=16, 8 warps (4x2), warp tile 32x24 (2x3 m16n8k8 atoms).
// smem k-permuted layout: elem k at offset (k&3)*4 + (k>>2), row pitch 20 floats,
// so one LDS.128 per fragment row feeds BOTH k-steps of a BK=16 slab.
template<int K, int N, bool GELU, bool ACC>
__global__ void __launch_bounds__(256) gemm_mma(const float* __restrict__ A,
                                                const float* __restrict__ W,
                                                const float* __restrict__ bias,
                                                float* __restrict__ C) {
    __shared__ __align__(16) uint32_t sA[2][128 * 20];
    __shared__ __align__(16) uint32_t sB[2][48 * 20];
    const int tid  = threadIdx.x;
    const int lane = tid & 31, warp = tid >> 5;
    const int wm = warp >> 1, wn = warp & 1;
    const size_t row0 = (size_t)blockIdx.x * 128;
    const int col0 = blockIdx.y * 48;

    // ldg mapping
    const int a_row = tid >> 2;            // 0..63 (and +64)
    const int a_kq  = tid & 3;             // k-chunk of 4
    const int b_kr  = tid / 12;            // 0..15 (tid<192)
    const int b_nc  = (tid % 12) * 4;      // 0..44

    float acc[2][3][4];
#pragma unroll
    for (int m = 0; m < 2; m++)
#pragma unroll
        for (int n = 0; n < 3; n++)
#pragma unroll
            for (int i = 0; i < 4; i++) acc[m][n][i] = 0.f;

    float4 a0v, a1v, bv;
    bv = make_float4(0.f, 0.f, 0.f, 0.f);

    // ---- stage loaders ----
    auto LDG = [&](int s) {
        const float* Ab = A + (row0 + a_row) * K + s * 16 + a_kq * 4;
        a0v = *(const float4*)Ab;
        a1v = *(const float4*)(Ab + (size_t)64 * K);
        if (tid < 192)
            bv = *(const float4*)(W + (size_t)(s * 16 + b_kr) * N + col0 + b_nc);
    };
    auto STS = [&](int b) {
        uint32_t* da = &sA[b][a_row * 20 + a_kq];
        da[0]  = f2tf(a0v.x);
        da[4]  = f2tf(a0v.y);
        da[8]  = f2tf(a0v.z);
        da[12] = f2tf(a0v.w);
        uint32_t* da2 = da + 64 * 20;
        da2[0]  = f2tf(a1v.x);
        da2[4]  = f2tf(a1v.y);
        da2[8]  = f2tf(a1v.z);
        da2[12] = f2tf(a1v.w);
        if (tid < 192) {
            const int perm = (b_kr & 3) * 4 + (b_kr >> 2);
            uint32_t* db = &sB[b][b_nc * 20 + perm];
            db[0]  = f2tf(bv.x);
            db[20] = f2tf(bv.y);
            db[40] = f2tf(bv.z);
            db[60] = f2tf(bv.w);
        }
    };
    auto COMPUTE = [&](int b) {
        uint4 af[2][2];
        uint4 bf[3];
#pragma unroll
        for (int m = 0; m < 2; m++) {
            const int r = wm * 32 + m * 16 + (lane >> 2);
            af[m][0] = *(const uint4*)&sA[b][r * 20 + (lane & 3) * 4];
            af[m][1] = *(const uint4*)&sA[b][(r + 8) * 20 + (lane & 3) * 4];
        }
#pragma unroll
        for (int n = 0; n < 3; n++) {
            const int nn = wn * 24 + n * 8 + (lane >> 2);
            bf[n] = *(const uint4*)&sB[b][nn * 20 + (lane & 3) * 4];
        }
#pragma unroll
        for (int m = 0; m < 2; m++)
#pragma unroll
            for (int n = 0; n < 3; n++)
                MMA_TF32(acc[m][n], af[m][0].x, af[m][1].x, af[m][0].y, af[m][1].y,
                         bf[n].x, bf[n].y);
#pragma unroll
        for (int m = 0; m < 2; m++)
#pragma unroll
            for (int n = 0; n < 3; n++)
                MMA_TF32(acc[m][n], af[m][0].z, af[m][1].z, af[m][0].w, af[m][1].w,
                         bf[n].z, bf[n].w);
    };

    constexpr int S = K / 16;
    LDG(0);
    STS(0);
    __syncthreads();
#pragma unroll 1
    for (int s = 0; s < S; ++s) {
        if (s + 1 < S) LDG(s + 1);
        COMPUTE(s & 1);
        if (s + 1 < S) {
            STS((s & 1) ^ 1);
            __syncthreads();
        }
    }

    // ---- epilogue ----
#pragma unroll
    for (int m = 0; m < 2; m++) {
        const size_t row = row0 + wm * 32 + m * 16 + (lane >> 2);
#pragma unroll
        for (int n = 0; n < 3; n++) {
            const int col = col0 + wn * 24 + n * 8 + ((lane & 3) << 1);
            const float b0 = bias[col], b1 = bias[col + 1];
            float v0 = acc[m][n][0] + b0;
            float v1 = acc[m][n][1] + b1;
            float v2 = acc[m][n][2] + b0;
            float v3 = acc[m][n][3] + b1;
            if (GELU) {
                v0 = gelu_exact(v0);
                v1 = gelu_exact(v1);
                v2 = gelu_exact(v2);
                v3 = gelu_exact(v3);
            }
            float* p0 = C + row * N + col;
            float* p1 = p0 + (size_t)8 * N;
            if (ACC) {
                float2 o0 = *(float2*)p0, o1 = *(float2*)p1;
                v0 += o0.x;
                v1 += o0.y;
                v2 += o1.x;
                v3 += o1.y;
            }
            *(float2*)p0 = make_float2(v0, v1);
            *(float2*)p1 = make_float2(v2, v3);
        }
    }
}

// ---------------- transposes ----------------
__global__ void k_tin(const float* __restrict__ x) {
    __shared__ float sm[32][33];
    const int cf0 = blockIdx.x * 32, hw0 = blockIdx.y * 32, b = blockIdx.z;
    const int tx = threadIdx.x, ty = threadIdx.y;
#pragma unroll
    for (int yy = 0; yy < 4; yy++) {
        int cf = cf0 + ty + yy * 8;
        sm[ty + yy * 8][tx] = x[((size_t)b * 480 + cf) * 4096 + hw0 + tx];
    }
    __syncthreads();
#pragma unroll
    for (int yy = 0; yy < 4; yy++) {
        int hw = hw0 + ty + yy * 8;
        g_t[((size_t)b * 4096 + hw) * 480 + cf0 + tx] = sm[tx][ty + yy * 8];
    }
}

__global__ void k_catx(const float* __restrict__ x) {
    __shared__ float sm[32][33];
    const int c0 = blockIdx.x * 32, hw0 = blockIdx.y * 32, n = blockIdx.z;
    const int tx = threadIdx.x, ty = threadIdx.y;
#pragma unroll
    for (int yy = 0; yy < 4; yy++) {
        int c = c0 + ty + yy * 8;
        if (c < 48)
            sm[ty + yy * 8][tx] = x[((size_t)n * 48 + c) * 4096 + hw0 + tx];
    }
    __syncthreads();
#pragma unroll
    for (int yy = 0; yy < 4; yy++) {
        int hw = hw0 + ty + yy * 8;
        int c = c0 + tx;
        if (c < 48)
            g_cat[((size_t)n * 4096 + hw) * 96 + c] = sm[tx][ty + yy * 8];
    }
}

__global__ void k_catt() {
    size_t idx = (size_t)blockIdx.x * 256 + threadIdx.x;
    if (idx >= (size_t)TOK * 48) return;
    int f = (int)(idx % 48);
    size_t p = idx / 48;
    int hw = (int)(p & 4095);
    int n = (int)(p >> 12);
    int b = n / 10, s = n % 10;
    g_cat[p * 96 + 48 + f] = g_t[(((size_t)b * 4096 + hw) * 10 + s) * 48 + f];
}

__global__ void k_scw(const float* __restrict__ scw) {
    int idx = blockIdx.x * 256 + threadIdx.x;
    if (idx < 96 * 48) {
        int c = idx / 48, o = idx % 48;
        g_scw[c * 48 + o] = scw[o * 96 + c];
    }
}

__global__ void k_tout(float* __restrict__ out) {
    __shared__ float sm[32][33];
    const int hw0 = blockIdx.x * 32, c0 = blockIdx.y * 32, n = blockIdx.z;
    const int tx = threadIdx.x, ty = threadIdx.y;
#pragma unroll
    for (int yy = 0; yy < 4; yy++) {
        int c = c0 + tx;
        if (c < 48)
            sm[ty + yy * 8][tx] = g_res[((size_t)n * 4096 + hw0 + ty + yy * 8) * 48 + c];
    }
    __syncthreads();
#pragma unroll
    for (int yy = 0; yy < 4; yy++) {
        int c = c0 + ty + yy * 8;
        if (c < 48)
            out[((size_t)n * 48 + c) * 4096 + hw0 + tx] = sm[tx][ty + yy * 8];
    }
}

// ---------------- banded attention ----------------
__global__ void __launch_bounds__(256) k_attn() {
    extern __shared__ float sm[];
    float* sq = sm;
    float* so = sm + 23040;
    const int tid = threadIdx.x;
    const size_t tok0 = (size_t)blockIdx.x * 160;

    for (int i = tid; i < 23040; i += 256) sq[i] = g_qkv[tok0 * 144 + i];
    __syncthreads();

    if (tid < 128) {
        const int sl = tid >> 3, hh = tid & 7;
        const float* base = sq + sl * 1440;
        const float scale = 0.40824829046386301637f;
        for (int i = 0; i < SEQ; i++) {
            const float* ki = base + i * 144 + 48 + hh * 6;
            int jlo = (i > 0) ? i - 1 : 0;
            int jhi = (i < SEQ - 1) ? i + 1 : SEQ - 1;
            float lg[3];
            float mx = -1e30f;
            for (int j = jlo; j <= jhi; j++) {
                const float* qj = base + j * 144 + hh * 6;
                float d = 0.f;
#pragma unroll
                for (int dd = 0; dd < 6; dd++) d += ki[dd] * qj[dd];
                d *= scale;
                lg[j - jlo] = d;
                mx = fmaxf(mx, d);
            }
            float se = 0.f;
            for (int j = jlo; j <= jhi; j++) {
                lg[j - jlo] = expf(lg[j - jlo] - mx);
                se += lg[j - jlo];
            }
            float inv = 1.f / se;
#pragma unroll
            for (int dd = 0; dd < 6; dd++) {
                float o = 0.f;
                for (int j = jlo; j <= jhi; j++)
                    o += lg[j - jlo] * base[j * 144 + 96 + hh * 6 + dd];
                so[(sl * 10 + i) * 48 + hh * 6 + dd] = o * inv;
            }
        }
    }
    __syncthreads();
    for (int i = tid; i < 7680; i += 256) g_o[tok0 * 48 + i] = so[i];
}

// ---------------- depthwise 3x3 conv ----------------
__global__ void __launch_bounds__(256) k_dw(const float* __restrict__ wdw,
                                            const float* __restrict__ bdw) {
    __shared__ float sw[864];
    __shared__ float sb[96];
    for (int i = threadIdx.x; i < 864; i += 256) sw[i] = wdw[i];
    for (int i = threadIdx.x; i < 96; i += 256) sb[i] = bdw[i];
    __syncthreads();

    size_t idx = (size_t)blockIdx.x * 256 + threadIdx.x;
    int c4 = (int)(idx % 24);
    size_t p = idx / 24;
    int w = (int)(p & 63);
    int h = (int)((p >> 6) & 63);
    int n = (int)(p >> 12);
    int c = c4 * 4;

    float4 acc = make_float4(sb[c], sb[c + 1], sb[c + 2], sb[c + 3]);
#pragma unroll
    for (int ky = 0; ky < 3; ky++) {
        int hh = h + ky - 1;
        if (hh < 0 || hh >= 64) continue;
#pragma unroll
        for (int kx = 0; kx < 3; kx++) {
            int ww = w + kx - 1;
            if (ww < 0 || ww >= 64) continue;
            const float4 v = *(const float4*)(g_cat + (((size_t)n * 4096 + hh * 64 + ww) * 96 + c));
            int wi = ky * 3 + kx;
            acc.x = fmaf(v.x, sw[(c + 0) * 9 + wi], acc.x);
            acc.y = fmaf(v.y, sw[(c + 1) * 9 + wi], acc.y);
            acc.z = fmaf(v.z, sw[(c + 2) * 9 + wi], acc.z);
            acc.w = fmaf(v.w, sw[(c + 3) * 9 + wi], acc.w);
        }
    }
    *(float4*)(g_z + p * 96 + c) = acc;
}

// ---------------- LayerNorm ----------------
__global__ void __launch_bounds__(128) k_ln(const float* __restrict__ gam,
                                            const float* __restrict__ bet) {
    const int row = blockIdx.x * 4 + (threadIdx.x >> 5);
    const int lane = threadIdx.x & 31;
    float* z = g_z + (size_t)row * 96;
    float x0 = z[lane], x1 = z[lane + 32], x2 = z[lane + 64];
    float s = x0 + x1 + x2;
#pragma unroll
    for (int o = 16; o; o >>= 1) s += __shfl_xor_sync(0xffffffffu, s, o);
    float mu = s * (1.f / 96.f);
    float d0 = x0 - mu, d1 = x1 - mu, d2 = x2 - mu;
    float q = d0 * d0 + d1 * d1 + d2 * d2;
#pragma unroll
    for (int o = 16; o; o >>= 1) q += __shfl_xor_sync(0xffffffffu, q, o);
    float rs = rsqrtf(q * (1.f / 96.f) + 1e-6f);
    z[lane]      = d0 * rs * gam[lane]      + bet[lane];
    z[lane + 32] = d1 * rs * gam[lane + 32] + bet[lane + 32];
    z[lane + 64] = d2 * rs * gam[lane + 64] + bet[lane + 64];
}

// ---------------- host launcher ----------------
extern "C" void kernel_launch(void* const* d_in, const int* in_sizes, int n_in,
                              void* d_out, int out_size) {
    const float* x      = (const float*)d_in[0];
    const float* qkv_w  = (const float*)d_in[1];
    const float* qkv_b  = (const float*)d_in[2];
    const float* proj_w = (const float*)d_in[3];
    const float* proj_b = (const float*)d_in[4];
    const float* ff1_w  = (const float*)d_in[5];
    const float* ff1_b  = (const float*)d_in[6];
    const float* ff2_w  = (const float*)d_in[7];
    const float* ff2_b  = (const float*)d_in[8];
    const float* dw_w   = (const float*)d_in[9];
    const float* dw_b   = (const float*)d_in[10];
    const float* ln_g   = (const float*)d_in[11];
    const float* ln_b   = (const float*)d_in[12];
    const float* pw1_w  = (const float*)d_in[13];
    const float* pw1_b  = (const float*)d_in[14];
    const float* pw2_w  = (const float*)d_in[15];
    const float* pw2_b  = (const float*)d_in[16];
    const float* sc_w   = (const float*)d_in[17];
    const float* sc_b   = (const float*)d_in[18];
    float* out = (float*)d_out;

    static float *pt = nullptr, *pqkv, *po, *ph, *pcat, *pz, *pres, *pscw;
    static bool init = false;
    if (!init) {
        cudaGetSymbolAddress((void**)&pt,   g_t);
        cudaGetSymbolAddress((void**)&pqkv, g_qkv);
        cudaGetSymbolAddress((void**)&po,   g_o);
        cudaGetSymbolAddress((void**)&ph,   g_h);
        cudaGetSymbolAddress((void**)&pcat, g_cat);
        cudaGetSymbolAddress((void**)&pz,   g_z);
        cudaGetSymbolAddress((void**)&pres, g_res);
        cudaGetSymbolAddress((void**)&pscw, g_scw);
        cudaFuncSetAttribute(k_attn, cudaFuncAttributeMaxDynamicSharedMemorySize, 122880);
        init = true;
    }

    const dim3 tb32(32, 8);
    k_tin<<<dim3(15, 128, BB), tb32>>>(x);

    for (int l = 0; l < 2; l++) {
        gemm_mma<48, 144, false, false><<<dim3(2560, 3), 256>>>(pt, qkv_w + l * 48 * 144, qkv_b + l * 144, pqkv);
        k_attn<<<2048, 256, 122880>>>();
        gemm_mma<48, 48, false, true><<<dim3(2560, 1), 256>>>(po, proj_w + l * 48 * 48, proj_b + l * 48, pt);
        gemm_mma<48, 192, true, false><<<dim3(2560, 4), 256>>>(pt, ff1_w + l * 48 * 192, ff1_b + l * 192, ph);
        gemm_mma<192, 48, false, true><<<dim3(2560, 1), 256>>>(ph, ff2_w + l * 192 * 48, ff2_b + l * 48, pt);
    }

    k_catx<<<dim3(2, 128, 80), tb32>>>(x);
    k_catt<<<61440, 256>>>();
    k_scw<<<18, 256>>>(sc_w);

    k_dw<<<30720, 256>>>(dw_w, dw_b);
    k_ln<<<81920, 128>>>(ln_g, ln_b);

    gemm_mma<96, 48, false, false><<<dim3(2560, 1), 256>>>(pcat, pscw, sc_b, pres);
    gemm_mma<96, 384, true, false><<<dim3(2560, 8), 256>>>(pz, pw1_w, pw1_b, ph);
    gemm_mma<384, 48, false, true><<<dim3(2560, 1), 256>>>(ph, pw2_w, pw2_b, pres);

    k_tout<<<dim3(128, 2, 80), tb32>>>(out);
}